// round 15
// baseline (speedup 1.0000x reference)
#include <cuda_runtime.h>
#include <cuda_fp16.h>

#define NN 100000
#define EE 1600000
#define IC 128
#define HH 64

// ---------------- device scratch (no allocs allowed) ----------------
// g_deg starts zero (static init) and the scan kernel re-zeroes it after
// reading, so "deg == 0 on entry" holds for every graph replay.
// g_count starts zero and k_fill (ordered after the scan) resets it.
__device__ __align__(16) int    g_deg[NN];
__device__ __align__(16) float  g_dis[NN];
__device__ __align__(16) int    g_bsum[512];
__device__ unsigned             g_count;
__device__ __align__(16) int    g_rowptr[NN + 1];
__device__ __align__(16) int    g_cursor[NN];
__device__ __align__(16) int2   g_csre[EE];      // {src, norm (fp32 bits)}
__device__ __align__(16) __half g_h0h[NN * HH];  // x @ W1 (fp16)
__device__ __align__(16) __half g_t1h[NN * HH];  // relu(agg1 + b1) (fp16)
__device__ __align__(16) __half g_ath[NN * HH];  // agg2 of t1 (fp16, pre-W2)
__device__ __align__(16) __half g_ph[NN * HH];   // p (fp16, bias folded)
__device__ __align__(16) __half g_qh[NN * HH];   // q (fp16, bias folded)
__device__ __align__(16) float  g_Wpq[2 * HH * HH]; // [Wp | Wq] = W2 @ [Wc1_top | Wc1_bot]
__device__ __align__(16) float  g_bp[HH];
__device__ __align__(16) float  g_bq[HH];

// ---------------- GEMM1: h0 = x @ W1 -> fp16 ; 128 rows/block ; fused histogram ----------------
__global__ __launch_bounds__(256) void k_gemm1(const float* __restrict__ x,
                                               const float* __restrict__ W1,
                                               const int* __restrict__ ei,
                                               int n, int E) {
    {
        int t = blockIdx.x * 256 + threadIdx.x;
        int stride = gridDim.x * 256;
        for (int e = t; e < E; e += stride)
            atomicAdd(&g_deg[ei[E + e]], 1);
    }
    __shared__ float Ws[IC * HH];
    __shared__ float xs[8][4 * IC];
    int tid = threadIdx.x;
    for (int i = tid; i < IC * HH / 4; i += 256)
        ((float4*)Ws)[i] = ((const float4*)W1)[i];
    __syncthreads();
    int w = tid >> 5, lane = tid & 31;
#pragma unroll 1
    for (int g = 0; g < 4; g++) {
        int r0 = blockIdx.x * 128 + w * 16 + g * 4;
        if (r0 >= n) continue;
        int nr = min(4, n - r0);
        const float4* xsrc = (const float4*)(x + (size_t)r0 * IC);
        float4* xd = (float4*)xs[w];
        for (int i = lane; i < nr * (IC / 4); i += 32) xd[i] = xsrc[i];
        __syncwarp();
        float acc[4][2] = {};
#pragma unroll 8
        for (int k = 0; k < IC; k++) {
            float w0 = Ws[k * HH + lane], w1 = Ws[k * HH + lane + 32];
#pragma unroll
            for (int rr = 0; rr < 4; rr++) {
                float xv = xs[w][rr * IC + k];
                acc[rr][0] = fmaf(xv, w0, acc[rr][0]);
                acc[rr][1] = fmaf(xv, w1, acc[rr][1]);
            }
        }
        for (int rr = 0; rr < nr; rr++) {
            int r = r0 + rr;
            g_h0h[r * HH + lane]      = __float2half(acc[rr][0]);
            g_h0h[r * HH + lane + 32] = __float2half(acc[rr][1]);
        }
        __syncwarp();
    }
}

// ---------------- fused scan (blocks < nb) + wcomb (blocks >= nb) ----------------
// Scan blocks: local scan of deg -> publish block sum -> wait for all scan
// blocks (all blocks co-resident: 48KB smem = 4 blocks/SM = 592 >= grid) ->
// sum predecessor aggregates -> write rowptr/cursor. Also computes dis and
// resets deg. g_count is reset by k_fill (strictly ordered after).
__global__ __launch_bounds__(256) void k_scanall(int n, int E, int nb,
                                                 const float* __restrict__ W2,
                                                 const float* __restrict__ b2,
                                                 const float* __restrict__ Wc1,
                                                 const float* __restrict__ bc1) {
    __shared__ float smem[12 * 1024];   // 48 KB
    int tid = threadIdx.x;
    int b = blockIdx.x;
    if (b < nb) {
        int* sh = (int*)smem;
        int i = b * 256 + tid;
        int v = (i < n) ? g_deg[i] : 0;
        if (i < n) {
            g_dis[i] = rsqrtf((float)(v + 1));
            g_deg[i] = 0;                       // reset for next replay
        }
        sh[tid] = v;
        __syncthreads();
        int acc = v;
#pragma unroll
        for (int o = 1; o < 256; o <<= 1) {
            int t = (tid >= o) ? sh[tid - o] : 0;
            __syncthreads();
            acc += t; sh[tid] = acc;
            __syncthreads();
        }
        int excl = acc - v;
        int bsum = sh[255];
        if (tid == 0) {
            g_bsum[b] = bsum;
            __threadfence();
            atomicAdd(&g_count, 1u);
            // spin until all scan blocks have published
            volatile unsigned* vc = &g_count;
            while (*vc < (unsigned)nb) { }
        }
        __syncthreads();
        __threadfence();
        // sum predecessor block aggregates (parallel over threads)
        int part = 0;
        for (int j = tid; j < b; j += 256) part += g_bsum[j];
        __syncthreads();                 // sh no longer needed for scan values
        sh[tid] = part;
        __syncthreads();
#pragma unroll
        for (int o = 128; o > 0; o >>= 1) {
            if (tid < o) sh[tid] += sh[tid + o];
            __syncthreads();
        }
        int bpre = sh[0];
        if (i < n) {
            int r = excl + bpre;
            g_rowptr[i] = r;
            g_cursor[i] = r;
        }
        if (i == 0) g_rowptr[n] = E;
    } else {
        // wcomb: Wpq = W2 @ [Wc1_top | Wc1_bot], 8 k-rows per block
        float* sW2  = smem;              // 16 KB
        float* sWc1 = smem + HH * HH;    // 32 KB
        for (int i = tid; i < HH * HH / 4; i += 256)
            ((float4*)sW2)[i] = ((const float4*)W2)[i];
        for (int i = tid; i < 2 * HH * HH / 4; i += 256)
            ((float4*)sWc1)[i] = ((const float4*)Wc1)[i];
        __syncthreads();
        int kbase = (b - nb) * 8;
        for (int idx = tid; idx < 8 * HH; idx += 256) {
            int k = kbase + (idx >> 6), c = idx & 63;
            float sp = 0.f, sq = 0.f;
#pragma unroll 8
            for (int j = 0; j < HH; j++) {
                float w = sW2[k * HH + j];
                sp = fmaf(w, sWc1[j * HH + c], sp);
                sq = fmaf(w, sWc1[(HH + j) * HH + c], sq);
            }
            g_Wpq[k * HH + c]           = sp;
            g_Wpq[HH * HH + k * HH + c] = sq;
        }
        if (b == nb && tid < HH) {
            float sp = bc1[tid], sq = 0.f;
            for (int j = 0; j < HH; j++) {
                float bb = b2[j];
                sp = fmaf(bb, sWc1[j * HH + tid], sp);
                sq = fmaf(bb, sWc1[(HH + j) * HH + tid], sq);
            }
            g_bp[tid] = sp;
            g_bq[tid] = sq;
        }
    }
}

// ---------------- CSR fill: one STG.64 per edge ; resets g_count ----------------
__global__ void k_fill(const int* __restrict__ ei, int E) {
    if (blockIdx.x == 0 && threadIdx.x == 0) g_count = 0u;  // for next replay
    int e = blockIdx.x * 256 + threadIdx.x;
    if (e >= E) return;
    int s = ei[e];
    int d = ei[E + e];
    int pos = atomicAdd(&g_cursor[d], 1);
    int2 v;
    v.x = s;
    v.y = __float_as_int(g_dis[s] * g_dis[d]);
    g_csre[pos] = v;
}

// ---------------- CSR gather on fp16 rows (half2 lanes, 4-edge unroll) ----------------
template<int LAYER>
__global__ __launch_bounds__(256) void k_gather(const float* __restrict__ bias, int n) {
    int w = threadIdx.x >> 5, lane = threadIdx.x & 31;
    int node = blockIdx.x * 8 + w;
    if (node >= n) return;
    const __half2* h = (const __half2*)(LAYER ? g_t1h : g_h0h);
    float dd = g_dis[node];
    float d2 = dd * dd;
    float2 self = __half22float2(h[node * 32 + lane]);
    float ax = self.x * d2, ay = self.y * d2;
    int i = g_rowptr[node], end = g_rowptr[node + 1];
    for (; i + 4 <= end; i += 4) {
        int2 e0 = g_csre[i],     e1 = g_csre[i + 1];
        int2 e2 = g_csre[i + 2], e3 = g_csre[i + 3];
        float n0 = __int_as_float(e0.y), n1 = __int_as_float(e1.y);
        float n2 = __int_as_float(e2.y), n3 = __int_as_float(e3.y);
        float2 v0 = __half22float2(h[e0.x * 32 + lane]);
        float2 v1 = __half22float2(h[e1.x * 32 + lane]);
        float2 v2 = __half22float2(h[e2.x * 32 + lane]);
        float2 v3 = __half22float2(h[e3.x * 32 + lane]);
        ax = fmaf(v0.x, n0, ax); ay = fmaf(v0.y, n0, ay);
        ax = fmaf(v1.x, n1, ax); ay = fmaf(v1.y, n1, ay);
        ax = fmaf(v2.x, n2, ax); ay = fmaf(v2.y, n2, ay);
        ax = fmaf(v3.x, n3, ax); ay = fmaf(v3.y, n3, ay);
    }
    for (; i < end; i++) {
        int2 e0 = g_csre[i];
        float n0 = __int_as_float(e0.y);
        float2 v0 = __half22float2(h[e0.x * 32 + lane]);
        ax = fmaf(v0.x, n0, ax); ay = fmaf(v0.y, n0, ay);
    }
    if (LAYER == 0) {
        float2 bb = __ldg((const float2*)bias + lane);
        float rx = fmaxf(ax + bb.x, 0.f);
        float ry = fmaxf(ay + bb.y, 0.f);
        ((__half2*)g_t1h)[node * 32 + lane] = __floats2half2_rn(rx, ry);
    } else {
        ((__half2*)g_ath)[node * 32 + lane] = __floats2half2_rn(ax, ay);
    }
}

// ---------------- p/q projection: 128 rows/block, fp16 input ----------------
__global__ __launch_bounds__(256) void k_pqc(int n) {
    __shared__ float Ws[2 * HH * HH];   // 32 KB
    __shared__ float hs[8][4 * HH];     // 8 KB
    int tid = threadIdx.x;
    for (int i = tid; i < 2 * HH * HH / 4; i += 256)
        ((float4*)Ws)[i] = ((const float4*)g_Wpq)[i];
    __syncthreads();
    int w = tid >> 5, lane = tid & 31;
    float p0 = g_bp[lane], p1 = g_bp[lane + 32];
    float q0 = g_bq[lane], q1 = g_bq[lane + 32];
#pragma unroll 1
    for (int g = 0; g < 4; g++) {
        int r0 = blockIdx.x * 128 + w * 16 + g * 4;
        if (r0 >= n) continue;
        int nr = min(4, n - r0);
        const __half2* hsrc = (const __half2*)g_ath + (size_t)r0 * 32;
        for (int i = lane; i < nr * 32; i += 32) {
            float2 f = __half22float2(hsrc[i]);
            hs[w][i * 2]     = f.x;
            hs[w][i * 2 + 1] = f.y;
        }
        __syncwarp();
        float ap[4][2] = {}, aq[4][2] = {};
#pragma unroll 4
        for (int k = 0; k < HH; k++) {
            float wp0 = Ws[k * HH + lane],        wp1 = Ws[k * HH + lane + 32];
            float wq0 = Ws[(HH + k) * HH + lane], wq1 = Ws[(HH + k) * HH + lane + 32];
#pragma unroll
            for (int rr = 0; rr < 4; rr++) {
                float hv = hs[w][rr * HH + k];
                ap[rr][0] = fmaf(hv, wp0, ap[rr][0]);
                ap[rr][1] = fmaf(hv, wp1, ap[rr][1]);
                aq[rr][0] = fmaf(hv, wq0, aq[rr][0]);
                aq[rr][1] = fmaf(hv, wq1, aq[rr][1]);
            }
        }
        for (int rr = 0; rr < nr; rr++) {
            int r = r0 + rr;
            g_ph[r * HH + lane]      = __float2half(ap[rr][0] + p0);
            g_ph[r * HH + lane + 32] = __float2half(ap[rr][1] + p1);
            g_qh[r * HH + lane]      = __float2half(aq[rr][0] + q0);
            g_qh[r * HH + lane + 32] = __float2half(aq[rr][1] + q1);
        }
        __syncwarp();
    }
}

// ---------------- edge classifier: 8 lanes x 4 edges, 8 LDG.128 in flight ----------------
__global__ __launch_bounds__(256) void k_cls(const int* __restrict__ ei,
                                             const float* __restrict__ Wc2,
                                             const float* __restrict__ bc2,
                                             float2* __restrict__ out, int E) {
    int t = blockIdx.x * 256 + threadIdx.x;
    int e0 = (t >> 3) * 4;          // E divisible by 4
    if (e0 >= E) return;
    int l = t & 7;
    int4 ss = *(const int4*)(ei + e0);
    int4 dd = *(const int4*)(ei + E + e0);
    uint4 pv0 = *(const uint4*)(g_ph + (size_t)ss.x * HH + l * 8);
    uint4 qv0 = *(const uint4*)(g_qh + (size_t)dd.x * HH + l * 8);
    uint4 pv1 = *(const uint4*)(g_ph + (size_t)ss.y * HH + l * 8);
    uint4 qv1 = *(const uint4*)(g_qh + (size_t)dd.y * HH + l * 8);
    uint4 pv2 = *(const uint4*)(g_ph + (size_t)ss.z * HH + l * 8);
    uint4 qv2 = *(const uint4*)(g_qh + (size_t)dd.z * HH + l * 8);
    uint4 pv3 = *(const uint4*)(g_ph + (size_t)ss.w * HH + l * 8);
    uint4 qv3 = *(const uint4*)(g_qh + (size_t)dd.w * HH + l * 8);
    const __half2* pp0 = (const __half2*)&pv0;
    const __half2* qq0 = (const __half2*)&qv0;
    const __half2* pp1 = (const __half2*)&pv1;
    const __half2* qq1 = (const __half2*)&qv1;
    const __half2* pp2 = (const __half2*)&pv2;
    const __half2* qq2 = (const __half2*)&qv2;
    const __half2* pp3 = (const __half2*)&pv3;
    const __half2* qq3 = (const __half2*)&qv3;
    float a0 = 0.f, a1 = 0.f, b0 = 0.f, b1 = 0.f;
    float c0 = 0.f, c1 = 0.f, d0 = 0.f, d1 = 0.f;
#pragma unroll
    for (int j = 0; j < 4; j++) {
        int c = l * 8 + j * 2;
        float2 wA = __ldg((const float2*)Wc2 + c);
        float2 wB = __ldg((const float2*)Wc2 + c + 1);
        {
            float2 pa = __half22float2(pp0[j]);
            float2 qa = __half22float2(qq0[j]);
            float u0 = fmaxf(pa.x + qa.x, 0.f);
            float u1 = fmaxf(pa.y + qa.y, 0.f);
            a0 += u0 * wA.x + u1 * wB.x;
            a1 += u0 * wA.y + u1 * wB.y;
        }
        {
            float2 pa = __half22float2(pp1[j]);
            float2 qa = __half22float2(qq1[j]);
            float u0 = fmaxf(pa.x + qa.x, 0.f);
            float u1 = fmaxf(pa.y + qa.y, 0.f);
            b0 += u0 * wA.x + u1 * wB.x;
            b1 += u0 * wA.y + u1 * wB.y;
        }
        {
            float2 pa = __half22float2(pp2[j]);
            float2 qa = __half22float2(qq2[j]);
            float u0 = fmaxf(pa.x + qa.x, 0.f);
            float u1 = fmaxf(pa.y + qa.y, 0.f);
            c0 += u0 * wA.x + u1 * wB.x;
            c1 += u0 * wA.y + u1 * wB.y;
        }
        {
            float2 pa = __half22float2(pp3[j]);
            float2 qa = __half22float2(qq3[j]);
            float u0 = fmaxf(pa.x + qa.x, 0.f);
            float u1 = fmaxf(pa.y + qa.y, 0.f);
            d0 += u0 * wA.x + u1 * wB.x;
            d1 += u0 * wA.y + u1 * wB.y;
        }
    }
#pragma unroll
    for (int o = 4; o > 0; o >>= 1) {
        a0 += __shfl_down_sync(0xffffffffu, a0, o, 8);
        a1 += __shfl_down_sync(0xffffffffu, a1, o, 8);
        b0 += __shfl_down_sync(0xffffffffu, b0, o, 8);
        b1 += __shfl_down_sync(0xffffffffu, b1, o, 8);
        c0 += __shfl_down_sync(0xffffffffu, c0, o, 8);
        c1 += __shfl_down_sync(0xffffffffu, c1, o, 8);
        d0 += __shfl_down_sync(0xffffffffu, d0, o, 8);
        d1 += __shfl_down_sync(0xffffffffu, d1, o, 8);
    }
    if (l == 0) {
        float z0 = __ldg(&bc2[0]), z1 = __ldg(&bc2[1]);
        float4 r0, r1;
        r0.x = a0 + z0; r0.y = a1 + z1;
        r0.z = b0 + z0; r0.w = b1 + z1;
        r1.x = c0 + z0; r1.y = c1 + z1;
        r1.z = d0 + z0; r1.w = d1 + z1;
        *(float4*)(out + e0)     = r0;
        *(float4*)(out + e0 + 2) = r1;
    }
}

// ---------------- launch ----------------
extern "C" void kernel_launch(void* const* d_in, const int* in_sizes, int n_in,
                              void* d_out, int out_size) {
    const float* x   = (const float*)d_in[0];
    const int*   ei  = (const int*)d_in[1];   // int32 edge_index (verified R4+)
    const float* W1  = (const float*)d_in[2];
    const float* b1  = (const float*)d_in[3];
    const float* W2  = (const float*)d_in[4];
    const float* b2  = (const float*)d_in[5];
    const float* Wc1 = (const float*)d_in[6];
    const float* bc1 = (const float*)d_in[7];
    const float* Wc2 = (const float*)d_in[8];
    const float* bc2 = (const float*)d_in[9];

    int N = in_sizes[0] / IC;   // 100000
    int E = in_sizes[1] / 2;    // 1600000
    int nb = (N + 255) / 256;   // 391

    k_gemm1<<<(N + 127) / 128, 256>>>(x, W1, ei, N, E);     // + degree histogram
    k_scanall<<<nb + 8, 256>>>(N, E, nb, W2, b2, Wc1, bc1); // scan + dis + cursor + wcomb
    k_fill<<<(E + 255) / 256, 256>>>(ei, E);                // + resets g_count

    k_gather<0><<<(N + 7) / 8, 256>>>(b1, N);
    k_gather<1><<<(N + 7) / 8, 256>>>(nullptr, N);
    k_pqc<<<(N + 127) / 128, 256>>>(N);
    k_cls<<<(int)(((long long)E * 2 + 255) / 256), 256>>>(ei, Wc2, bc2, (float2*)d_out, E);
}